// round 10
// baseline (speedup 1.0000x reference)
#include <cuda_runtime.h>
#include <cuda_pipeline.h>
#include <cstdint>
#include <math.h>

#define NVARS 1024
#define BATCH 64
#define KDIM  32
#define NIN   768
#define SWEEPS 10
#define PI_F 3.14159274101257324f

// dynamic smem layout (floats)
#define F_CBUF 0            // 12 rows * 1024  (3-group cp.async ring)
#define F_SVD  12288        // 7 * 1024 coupling-scalar tables
#define F_PT   19456        // 2 * 4 * 512 partials
#define F_VNB  23552        // 2 * 4 * 32 vn broadcast
#define F_VOLD 23808        // 2 * 4 * 32 stale-value broadcast
#define F_LST  24064        // 1024 ushort = 512 floats
#define SMEM_FLOATS 24576
#define SMEM_BYTES (SMEM_FLOATS * 4)

// ---------------- persistent scratch (no runtime allocation) ----------------
__device__ float V_g[BATCH * NVARS * KDIM];     // 8 MB
__device__ float v0_g[BATCH * KDIM];
__device__ unsigned short list_g[BATCH * NVARS];
__device__ int cnt_g[BATCH];

// ---------------- f32x2 helpers ----------------
__device__ __forceinline__ void ffma2(unsigned long long &d, unsigned long long a,
                                      unsigned long long b) {
    asm("fma.rn.f32x2 %0, %1, %2, %3;" : "=l"(d) : "l"(a), "l"(b), "l"(d));
}
__device__ __forceinline__ void fadd2(unsigned long long &d, unsigned long long a,
                                      unsigned long long b) {
    asm("add.rn.f32x2 %0, %1, %2;" : "=l"(d) : "l"(a), "l"(b));
}
__device__ __forceinline__ unsigned long long pk2(float lo, float hi) {
    unsigned long long r;
    asm("mov.b64 %0, {%1, %2};" : "=l"(r) : "f"(lo), "f"(hi));
    return r;
}
__device__ __forceinline__ void up2(unsigned long long v, float &lo, float &hi) {
    asm("mov.b64 {%0, %1}, %2;" : "=f"(lo), "=f"(hi) : "l"(v));
}

__device__ __forceinline__ float warp_sum(float v) {
#pragma unroll
    for (int off = 16; off; off >>= 1)
        v += __shfl_xor_sync(0xffffffffu, v, off);
    return v;
}

__device__ __forceinline__ float dot_row(const ulonglong2* __restrict__ Cp,
                                         const unsigned long long (&v2)[32]) {
    unsigned long long a0 = 0ull, a1 = 0ull, a2 = 0ull, a3 = 0ull;
#pragma unroll
    for (int q = 0; q < 16; q++) {
        ulonglong2 cc = Cp[q];
        ffma2(((q & 1) ? a2 : a0), cc.x, v2[2 * q]);
        ffma2(((q & 1) ? a3 : a1), cc.y, v2[2 * q + 1]);
    }
    fadd2(a0, a0, a2); fadd2(a1, a1, a3); fadd2(a0, a0, a1);
    float x, y; up2(a0, x, y);
    return x + y;
}

// jump-table insert/extract (p0 is warp-uniform -> BRX)
__device__ __forceinline__ void insert_sw(unsigned long long (&v2)[32], int j, float vn) {
    const int p0 = j >> 1;
    const bool hi = (j & 1) != 0;
#define INS_CASE(P) case P: { float x, y; up2(v2[P], x, y); \
                              if (hi) y = vn; else x = vn;  \
                              v2[P] = pk2(x, y); } break;
    switch (p0) {
        INS_CASE(0)  INS_CASE(1)  INS_CASE(2)  INS_CASE(3)
        INS_CASE(4)  INS_CASE(5)  INS_CASE(6)  INS_CASE(7)
        INS_CASE(8)  INS_CASE(9)  INS_CASE(10) INS_CASE(11)
        INS_CASE(12) INS_CASE(13) INS_CASE(14) INS_CASE(15)
        INS_CASE(16) INS_CASE(17) INS_CASE(18) INS_CASE(19)
        INS_CASE(20) INS_CASE(21) INS_CASE(22) INS_CASE(23)
        INS_CASE(24) INS_CASE(25) INS_CASE(26) INS_CASE(27)
        INS_CASE(28) INS_CASE(29) INS_CASE(30) INS_CASE(31)
    }
#undef INS_CASE
}

__device__ __forceinline__ float extract_sw(const unsigned long long (&v2)[32], int j) {
    const int p0 = j >> 1;
    const bool hi = (j & 1) != 0;
    float r = 0.0f;
#define EXT_CASE(P) case P: { float x, y; up2(v2[P], x, y); r = hi ? y : x; } break;
    switch (p0) {
        EXT_CASE(0)  EXT_CASE(1)  EXT_CASE(2)  EXT_CASE(3)
        EXT_CASE(4)  EXT_CASE(5)  EXT_CASE(6)  EXT_CASE(7)
        EXT_CASE(8)  EXT_CASE(9)  EXT_CASE(10) EXT_CASE(11)
        EXT_CASE(12) EXT_CASE(13) EXT_CASE(14) EXT_CASE(15)
        EXT_CASE(16) EXT_CASE(17) EXT_CASE(18) EXT_CASE(19)
        EXT_CASE(20) EXT_CASE(21) EXT_CASE(22) EXT_CASE(23)
        EXT_CASE(24) EXT_CASE(25) EXT_CASE(26) EXT_CASE(27)
        EXT_CASE(28) EXT_CASE(29) EXT_CASE(30) EXT_CASE(31)
    }
#undef EXT_CASE
    return r;
}

// ---------------- threefry2x32 core, exact JAX schedule ----------------
__device__ __forceinline__ void tf2x32(unsigned k0, unsigned k1,
                                       unsigned x0, unsigned x1,
                                       unsigned &y0, unsigned &y1) {
    unsigned ks2 = k0 ^ k1 ^ 0x1BD11BDAu;
    x0 += k0; x1 += k1;
#define TFR(r) { x0 += x1; x1 = (x1 << r) | (x1 >> (32 - r)); x1 ^= x0; }
    TFR(13) TFR(15) TFR(26) TFR(6)  x0 += k1;  x1 += ks2 + 1u;
    TFR(17) TFR(29) TFR(16) TFR(24) x0 += ks2; x1 += k0 + 2u;
    TFR(13) TFR(15) TFR(26) TFR(6)  x0 += k0;  x1 += k1 + 3u;
    TFR(17) TFR(29) TFR(16) TFR(24) x0 += k1;  x1 += ks2 + 4u;
    TFR(13) TFR(15) TFR(26) TFR(6)  x0 += ks2; x1 += k0 + 5u;
#undef TFR
    y0 = x0; y1 = x1;
}

// PARTITIONABLE threefry (modern JAX default)
__device__ __forceinline__ void derive_keys(unsigned &k1a, unsigned &k1b,
                                            unsigned &k2a, unsigned &k2b) {
    tf2x32(0u, 42u, 0u, 0u, k1a, k1b);
    tf2x32(0u, 42u, 0u, 1u, k2a, k2b);
}

__device__ __forceinline__ unsigned tf_bits(unsigned ka, unsigned kb, unsigned e) {
    unsigned y0, y1;
    tf2x32(ka, kb, 0u, e, y0, y1);
    return y0 ^ y1;
}

__device__ __forceinline__ float bits_to_normal(unsigned bits) {
    float u01 = __fadd_rn(__uint_as_float((bits >> 9) | 0x3F800000u), -1.0f);
    float u = __fadd_rn(__fmul_rn(u01, 2.0f), -0.99999994f);
    u = fmaxf(u, -0.99999994f);
    float x = u;
    float xx = __fmul_rn(x, x);
    float w = -log1pf(-xx);
    float p;
    if (w < 5.0f) {
        w = __fadd_rn(w, -2.5f);
        p = 2.81022636e-08f;
        p = __fadd_rn(__fmul_rn(p, w), 3.43273939e-07f);
        p = __fadd_rn(__fmul_rn(p, w), -3.5233877e-06f);
        p = __fadd_rn(__fmul_rn(p, w), -4.39150654e-06f);
        p = __fadd_rn(__fmul_rn(p, w), 0.00021858087f);
        p = __fadd_rn(__fmul_rn(p, w), -0.00125372503f);
        p = __fadd_rn(__fmul_rn(p, w), -0.00417768164f);
        p = __fadd_rn(__fmul_rn(p, w), 0.246640727f);
        p = __fadd_rn(__fmul_rn(p, w), 1.50140941f);
    } else {
        w = __fadd_rn(sqrtf(w), -3.0f);
        p = -0.000200214257f;
        p = __fadd_rn(__fmul_rn(p, w), 0.000100950558f);
        p = __fadd_rn(__fmul_rn(p, w), 0.00134934322f);
        p = __fadd_rn(__fmul_rn(p, w), -0.00367342844f);
        p = __fadd_rn(__fmul_rn(p, w), 0.00573950773f);
        p = __fadd_rn(__fmul_rn(p, w), -0.0076224613f);
        p = __fadd_rn(__fmul_rn(p, w), 0.00943887047f);
        p = __fadd_rn(__fmul_rn(p, w), 1.00167406f);
        p = __fadd_rn(__fmul_rn(p, w), 2.83297682f);
    }
    return __fmul_rn(1.41421354f, __fmul_rn(p, x));
}

// ---------------- fused init kernel: one CTA per batch, 1024 threads ----------------
__global__ void __launch_bounds__(1024, 1)
init_kernel(const float* __restrict__ z, const int* __restrict__ is_input) {
    __shared__ float v0s[32];
    const int b = blockIdx.x;
    const int w = threadIdx.x >> 5;
    const int l = threadIdx.x & 31;
    unsigned k1a, k1b, k2a, k2b; derive_keys(k1a, k1b, k2a, k2b);

    if (w == 0) {
        float n = bits_to_normal(tf_bits(k1a, k1b, (unsigned)(b * 32 + l)));
        float ss = warp_sum(__fmul_rn(n, n));
        float v0 = n / sqrtf(ss);
        v0s[l] = v0;
        v0_g[b * 32 + l] = v0;
    }
    __syncthreads();
    float v0l = v0s[l];

#pragma unroll 1
    for (int k = 0; k < 32; k++) {
        int n = w * 32 + k;
        unsigned e = ((unsigned)(b * 1024 + n)) * 32u + (unsigned)l;
        float r = bits_to_normal(tf_bits(k2a, k2b, e));
        float d = warp_sum(__fmul_rn(r, v0l));
        float rp = __fadd_rn(r, -__fmul_rn(d, v0l));
        float nr = sqrtf(warp_sum(__fmul_rn(rp, rp)));
        float R = rp / nr;

        float zf; int ii;
        if (n == 0)        { zf = 1.0f; ii = 1; }
        else if (n <= NIN) { zf = z[b * NIN + n - 1]; ii = is_input[b * NIN + n - 1]; }
        else               { zf = 0.0f; ii = 0; }

        float V;
        if (ii > 0) {
            float x = __fmul_rn(PI_F, zf);
            V = __fadd_rn(__fmul_rn(-cosf(x), v0l), __fmul_rn(sinf(x), R));
        } else {
            V = R;
        }
        if (n == 0) V = v0l;
        V_g[((size_t)b * 1024 + n) * 32 + l] = V;
    }

    // free list (warp 31)
    if (w == 31) {
        int m = 0;
        for (int base = 1; base < 1024; base += 32) {
            int n = base + l;
            bool f = (n < 1024) && (n > NIN || is_input[b * NIN + n - 1] == 0);
            unsigned msk = __ballot_sync(0xffffffffu, f);
            if (f) {
                int pos = m + __popc(msk & ((1u << l) - 1u));
                list_g[b * 1024 + pos] = (unsigned short)n;
            }
            m += __popc(msk);
        }
        if (l == 0) cnt_g[b] = m;
    }
}

// ---------------- mix kernel: S=4 batched, pipelined, register-vold ----------------
__global__ void __launch_bounds__(544, 1)
mix_kernel(const float* __restrict__ C,
           const float* __restrict__ z,
           const int* __restrict__ is_input,
           float* __restrict__ out) {
    extern __shared__ float sm[];
    unsigned short* lstS = (unsigned short*)&sm[F_LST];

    const int b = blockIdx.x;
    const int tid = threadIdx.x;
    const int w = tid >> 5;
    const int l = tid & 31;
    const bool dotw = (w < 16);

    __shared__ int scnt;
    for (int idx = tid; idx < 1024; idx += 544)
        lstS[idx] = list_g[b * 1024 + idx];
    if (tid == 0) scnt = cnt_g[b];
    __syncthreads();
    const int cnt = scnt;
    const int total = cnt * SWEEPS;
    const int P = (total + 3) / 4;

    // coupling tables svd[d-1][m] = C[lst[(m+d)%cnt], lst[m]], d=1..7
    for (int t = tid; t < 7 * cnt; t += 544) {
        int d = t / cnt + 1;
        int m = t - (d - 1) * cnt;
        int mp = m + d; if (mp >= cnt) mp -= cnt;
        sm[F_SVD + (d - 1) * 1024 + m] =
            __ldg(C + (size_t)lstS[mp] * NVARS + lstS[m]);
    }

    // V in registers: warp w owns rows [64w,64w+64), lane l = column l
    unsigned long long v2[32];
    if (dotw) {
#pragma unroll
        for (int p = 0; p < 32; p++) {
            int row = w * 64 + 2 * p;
            v2[p] = pk2(V_g[((size_t)b * 1024 + row) * 32 + l],
                        V_g[((size_t)b * 1024 + row + 1) * 32 + l]);
        }
    }
    __syncthreads();   // svd + lst ready

    // prologue staging: G1 -> slot1, G2 -> slot2
    if (tid < 256) {
#pragma unroll
        for (int s = 0; s < 4; s++)
            __pipeline_memcpy_async(&sm[F_CBUF + (4 + s) * 1024 + tid * 4],
                                    C + (size_t)lstS[(4 + s) % cnt] * NVARS + tid * 4, 16);
    }
    __pipeline_commit();
    if (tid < 256) {
#pragma unroll
        for (int s = 0; s < 4; s++)
            __pipeline_memcpy_async(&sm[F_CBUF + (8 + s) * 1024 + tid * 4],
                                    C + (size_t)lstS[(8 + s) % cnt] * NVARS + tid * 4, 16);
    }
    __pipeline_commit();

    // prologue dots for G0 from gmem + vold(G0) publish
    if (dotw) {
#pragma unroll
        for (int s = 0; s < 4; s++) {
            const ulonglong2* Cp = reinterpret_cast<const ulonglong2*>(
                C + (size_t)lstS[s] * NVARS + w * 64);
            sm[F_PT + 0 * 2048 + s * 512 + w * 32 + l] = dot_row(Cp, v2);
        }
#pragma unroll
        for (int s = 0; s < 4; s++) {
            int i = lstS[s];
            if (w == (i >> 6))
                sm[F_VOLD + 0 * 128 + s * 32 + l] = extract_sw(v2, i & 63);
        }
    }
    __pipeline_wait_prior(1);
    __syncthreads();

    int m_prev = 0, m_cur = 0, m_n1 = 4 % cnt, m_stage = 12 % cnt;
    float dvP[4] = {0.f, 0.f, 0.f, 0.f};

    for (int p = 0; p < P; p++) {
        const int rd = p & 1, wr = (p + 1) & 1;

        // stage G_{p+3} into ring slot p%3
        if (tid < 256) {
            int slot = p % 3;
#pragma unroll
            for (int s = 0; s < 4; s++) {
                int mq = m_stage + s; if (mq >= cnt) mq -= cnt;
                __pipeline_memcpy_async(&sm[F_CBUF + (slot * 4 + s) * 1024 + tid * 4],
                                        C + (size_t)lstS[mq] * NVARS + tid * 4, 16);
            }
        }
        __pipeline_commit();

        if (dotw) {
            // apply previous phase's 4 updates (G_{p-1})
            if (p > 0) {
#pragma unroll
                for (int s = 0; s < 4; s++) {
                    int mp = m_prev + s; if (mp >= cnt) mp -= cnt;
                    int i = lstS[mp];
                    if (w == (i >> 6))
                        insert_sw(v2, i & 63, sm[F_VNB + wr * 128 + s * 32 + l]);
                }
            }
            // dots for G_{p+1} from staged ring slot (p+1)%3
            int slotr = ((p + 1) % 3) * 4;
#pragma unroll
            for (int s = 0; s < 4; s++) {
                const ulonglong2* Cs = reinterpret_cast<const ulonglong2*>(
                    &sm[F_CBUF + (slotr + s) * 1024 + w * 64]);
                sm[F_PT + wr * 2048 + s * 512 + w * 32 + l] = dot_row(Cs, v2);
            }
            // publish vold for G_{p+1} (current register values = pre-update)
#pragma unroll
            for (int s = 0; s < 4; s++) {
                int mq = m_n1 + s; if (mq >= cnt) mq -= cnt;
                int i = lstS[mq];
                if (w == (i >> 6))
                    sm[F_VOLD + wr * 128 + s * 32 + l] = extract_sw(v2, i & 63);
            }
        } else if (w == 16) {
            // base sums (off-chain): tree + prev-group corrections
            float base[4];
#pragma unroll
            for (int s = 0; s < 4; s++) {
                const float* pr = &sm[F_PT + rd * 2048 + s * 512];
                float t0 = pr[0 * 32 + l],  t1 = pr[1 * 32 + l];
                float t2 = pr[2 * 32 + l],  t3 = pr[3 * 32 + l];
                float t4 = pr[4 * 32 + l],  t5 = pr[5 * 32 + l];
                float t6 = pr[6 * 32 + l],  t7 = pr[7 * 32 + l];
                float t8 = pr[8 * 32 + l],  t9 = pr[9 * 32 + l];
                float ta = pr[10 * 32 + l], tb = pr[11 * 32 + l];
                float tc = pr[12 * 32 + l], td = pr[13 * 32 + l];
                float te = pr[14 * 32 + l], tf = pr[15 * 32 + l];
                float g = (((t0 + t1) + (t2 + t3)) + ((t4 + t5) + (t6 + t7)))
                        + (((t8 + t9) + (ta + tb)) + ((tc + td) + (te + tf)));
#pragma unroll
                for (int sp = 0; sp < 4; sp++) {
                    int d = 4 + s - sp;
                    int mq = m_prev + sp; if (mq >= cnt) mq -= cnt;
                    g = fmaf(sm[F_SVD + (d - 1) * 1024 + mq], dvP[sp], g);
                }
                base[s] = g;
            }
            // serial chain: intra-group corrections + normalize
            float dv_new[4];
#pragma unroll
            for (int s = 0; s < 4; s++) {
                float g = base[s];
#pragma unroll
                for (int sp = 0; sp < 4; sp++)
                    if (sp < s) {
                        int d = s - sp;
                        int mq = m_cur + sp; if (mq >= cnt) mq -= cnt;
                        g = fmaf(sm[F_SVD + (d - 1) * 1024 + mq], dv_new[sp], g);
                    }
                float ss = warp_sum(g * g);
                ss = fmaxf(ss, 1e-24f);
                float vn = -g * rsqrtf(ss);
                sm[F_VNB + rd * 128 + s * 32 + l] = vn;
                dv_new[s] = vn - sm[F_VOLD + rd * 128 + s * 32 + l];
            }
#pragma unroll
            for (int s = 0; s < 4; s++) dvP[s] = dv_new[s];
        }

        __pipeline_wait_prior(1);
        __syncthreads();

        m_prev = m_cur; m_cur = m_n1;
        m_n1 += 4; if (m_n1 >= cnt) m_n1 -= cnt;
        m_stage += 4; if (m_stage >= cnt) m_stage -= cnt;
    }

    // apply pending last-phase updates (guard stream index < total)
    if (dotw) {
        int baseT = 4 * (P - 1);
        int basem = baseT % cnt;
        int vb = (P - 1) & 1;
#pragma unroll
        for (int s = 0; s < 4; s++) {
            if (baseT + s < total) {
                int mp = basem + s; if (mp >= cnt) mp -= cnt;
                int i = lstS[mp];
                if (w == (i >> 6))
                    insert_sw(v2, i & 63, sm[F_VNB + vb * 128 + s * 32 + l]);
            }
        }
    }

    // ---------------- epilogue: z_out[:, 1:769] ----------------
    if (dotw) {
        float v0l = v0_g[b * 32 + l];
        const float CLO = (float)(-1.0 + 1e-7);
        const float CHI = (float)( 1.0 - 1e-7);
#pragma unroll
        for (int j = 0; j < 64; j++) {
            int n = w * 64 + j;
            if (n >= 1 && n <= NIN) {
                float x, y; up2(v2[j >> 1], x, y);
                float Vv = (j & 1) ? y : x;
                float d = warp_sum(__fmul_rn(Vv, v0l));
                if (l == 0) {
                    int idx = b * NIN + n - 1;
                    float res;
                    if (is_input[idx] != 0) {
                        res = z[idx];
                    } else {
                        float ca = fminf(fmaxf(-d, CLO), CHI);
                        res = acosf(ca) / PI_F;
                    }
                    out[idx] = res;
                }
            }
        }
    }
}

// ---------------- launcher ----------------
extern "C" void kernel_launch(void* const* d_in, const int* in_sizes, int n_in,
                              void* d_out, int out_size) {
    const float* C        = (const float*)d_in[0];
    const float* z        = (const float*)d_in[1];
    const int*   is_input = (const int*)d_in[2];
    float* out = (float*)d_out;

    cudaFuncSetAttribute(mix_kernel,
                         cudaFuncAttributeMaxDynamicSharedMemorySize, SMEM_BYTES);

    init_kernel<<<BATCH, 1024>>>(z, is_input);
    mix_kernel<<<BATCH, 544, SMEM_BYTES>>>(C, z, is_input, out);
}

// round 11
// speedup vs baseline: 1.1094x; 1.1094x over previous
#include <cuda_runtime.h>
#include <cuda_pipeline.h>
#include <cstdint>
#include <math.h>

#define NVARS 1024
#define BATCH 64
#define KDIM  32
#define NIN   768
#define SWEEPS 10
#define PI_F 3.14159274101257324f
#define S 8

// dynamic smem layout (floats)
#define F_CBUF 0            // 24 rows * 1024  (3-group x 8-row cp.async ring)
#define F_SVD  24576        // 15 * 1024 coupling-scalar tables (distance 1..15)
#define F_PT   39936        // 2 * 8 * 512 partials
#define F_VNB  48128        // 2 * 8 * 32 vn broadcast
#define F_LST  48640        // 1024 ushort = 512 floats
#define SMEM_FLOATS 49152
#define SMEM_BYTES (SMEM_FLOATS * 4)   // 192 KB

// ---------------- persistent scratch (no runtime allocation) ----------------
__device__ float V_g[BATCH * NVARS * KDIM];     // 8 MB
__device__ float VH_g[BATCH * NVARS * KDIM];    // 8 MB value-history by list position
__device__ float v0_g[BATCH * KDIM];
__device__ unsigned short list_g[BATCH * NVARS];
__device__ int cnt_g[BATCH];

// ---------------- f32x2 helpers ----------------
__device__ __forceinline__ void ffma2(unsigned long long &d, unsigned long long a,
                                      unsigned long long b) {
    asm("fma.rn.f32x2 %0, %1, %2, %3;" : "=l"(d) : "l"(a), "l"(b), "l"(d));
}
__device__ __forceinline__ void fadd2(unsigned long long &d, unsigned long long a,
                                      unsigned long long b) {
    asm("add.rn.f32x2 %0, %1, %2;" : "=l"(d) : "l"(a), "l"(b));
}
__device__ __forceinline__ unsigned long long pk2(float lo, float hi) {
    unsigned long long r;
    asm("mov.b64 %0, {%1, %2};" : "=l"(r) : "f"(lo), "f"(hi));
    return r;
}
__device__ __forceinline__ void up2(unsigned long long v, float &lo, float &hi) {
    asm("mov.b64 {%0, %1}, %2;" : "=f"(lo), "=f"(hi) : "l"(v));
}

__device__ __forceinline__ float warp_sum(float v) {
#pragma unroll
    for (int off = 16; off; off >>= 1)
        v += __shfl_xor_sync(0xffffffffu, v, off);
    return v;
}

__device__ __forceinline__ float dot_row(const ulonglong2* __restrict__ Cp,
                                         const unsigned long long (&v2)[32]) {
    unsigned long long a0 = 0ull, a1 = 0ull, a2 = 0ull, a3 = 0ull;
#pragma unroll
    for (int q = 0; q < 16; q++) {
        ulonglong2 cc = Cp[q];
        ffma2(((q & 1) ? a2 : a0), cc.x, v2[2 * q]);
        ffma2(((q & 1) ? a3 : a1), cc.y, v2[2 * q + 1]);
    }
    fadd2(a0, a0, a2); fadd2(a1, a1, a3); fadd2(a0, a0, a1);
    float x, y; up2(a0, x, y);
    return x + y;
}

// predicated-chain insert (R7-verified form; ptxas emits pipelined ISETP+SEL)
__device__ __forceinline__ void insert_pred(unsigned long long (&v2)[32], int j, float vn) {
    int p0 = j >> 1;
#pragma unroll
    for (int p = 0; p < 32; p++)
        if (p == p0) {
            float x, y; up2(v2[p], x, y);
            if (j & 1) y = vn; else x = vn;
            v2[p] = pk2(x, y);
        }
}

// ---------------- threefry2x32 core, exact JAX schedule ----------------
__device__ __forceinline__ void tf2x32(unsigned k0, unsigned k1,
                                       unsigned x0, unsigned x1,
                                       unsigned &y0, unsigned &y1) {
    unsigned ks2 = k0 ^ k1 ^ 0x1BD11BDAu;
    x0 += k0; x1 += k1;
#define TFR(r) { x0 += x1; x1 = (x1 << r) | (x1 >> (32 - r)); x1 ^= x0; }
    TFR(13) TFR(15) TFR(26) TFR(6)  x0 += k1;  x1 += ks2 + 1u;
    TFR(17) TFR(29) TFR(16) TFR(24) x0 += ks2; x1 += k0 + 2u;
    TFR(13) TFR(15) TFR(26) TFR(6)  x0 += k0;  x1 += k1 + 3u;
    TFR(17) TFR(29) TFR(16) TFR(24) x0 += k1;  x1 += ks2 + 4u;
    TFR(13) TFR(15) TFR(26) TFR(6)  x0 += ks2; x1 += k0 + 5u;
#undef TFR
    y0 = x0; y1 = x1;
}

// PARTITIONABLE threefry (modern JAX default)
__device__ __forceinline__ void derive_keys(unsigned &k1a, unsigned &k1b,
                                            unsigned &k2a, unsigned &k2b) {
    tf2x32(0u, 42u, 0u, 0u, k1a, k1b);
    tf2x32(0u, 42u, 0u, 1u, k2a, k2b);
}

__device__ __forceinline__ unsigned tf_bits(unsigned ka, unsigned kb, unsigned e) {
    unsigned y0, y1;
    tf2x32(ka, kb, 0u, e, y0, y1);
    return y0 ^ y1;
}

__device__ __forceinline__ float bits_to_normal(unsigned bits) {
    float u01 = __fadd_rn(__uint_as_float((bits >> 9) | 0x3F800000u), -1.0f);
    float u = __fadd_rn(__fmul_rn(u01, 2.0f), -0.99999994f);
    u = fmaxf(u, -0.99999994f);
    float x = u;
    float xx = __fmul_rn(x, x);
    float w = -log1pf(-xx);
    float p;
    if (w < 5.0f) {
        w = __fadd_rn(w, -2.5f);
        p = 2.81022636e-08f;
        p = __fadd_rn(__fmul_rn(p, w), 3.43273939e-07f);
        p = __fadd_rn(__fmul_rn(p, w), -3.5233877e-06f);
        p = __fadd_rn(__fmul_rn(p, w), -4.39150654e-06f);
        p = __fadd_rn(__fmul_rn(p, w), 0.00021858087f);
        p = __fadd_rn(__fmul_rn(p, w), -0.00125372503f);
        p = __fadd_rn(__fmul_rn(p, w), -0.00417768164f);
        p = __fadd_rn(__fmul_rn(p, w), 0.246640727f);
        p = __fadd_rn(__fmul_rn(p, w), 1.50140941f);
    } else {
        w = __fadd_rn(sqrtf(w), -3.0f);
        p = -0.000200214257f;
        p = __fadd_rn(__fmul_rn(p, w), 0.000100950558f);
        p = __fadd_rn(__fmul_rn(p, w), 0.00134934322f);
        p = __fadd_rn(__fmul_rn(p, w), -0.00367342844f);
        p = __fadd_rn(__fmul_rn(p, w), 0.00573950773f);
        p = __fadd_rn(__fmul_rn(p, w), -0.0076224613f);
        p = __fadd_rn(__fmul_rn(p, w), 0.00943887047f);
        p = __fadd_rn(__fmul_rn(p, w), 1.00167406f);
        p = __fadd_rn(__fmul_rn(p, w), 2.83297682f);
    }
    return __fmul_rn(1.41421354f, __fmul_rn(p, x));
}

// ---------------- fused init kernel: one CTA per batch, 1024 threads ----------------
__global__ void __launch_bounds__(1024, 1)
init_kernel(const float* __restrict__ z, const int* __restrict__ is_input) {
    __shared__ float v0s[32];
    const int b = blockIdx.x;
    const int w = threadIdx.x >> 5;
    const int l = threadIdx.x & 31;
    unsigned k1a, k1b, k2a, k2b; derive_keys(k1a, k1b, k2a, k2b);

    if (w == 0) {
        float n = bits_to_normal(tf_bits(k1a, k1b, (unsigned)(b * 32 + l)));
        float ss = warp_sum(__fmul_rn(n, n));
        float v0 = n / sqrtf(ss);
        v0s[l] = v0;
        v0_g[b * 32 + l] = v0;
    }
    __syncthreads();
    float v0l = v0s[l];

#pragma unroll 1
    for (int k = 0; k < 32; k++) {
        int n = w * 32 + k;
        unsigned e = ((unsigned)(b * 1024 + n)) * 32u + (unsigned)l;
        float r = bits_to_normal(tf_bits(k2a, k2b, e));
        float d = warp_sum(__fmul_rn(r, v0l));
        float rp = __fadd_rn(r, -__fmul_rn(d, v0l));
        float nr = sqrtf(warp_sum(__fmul_rn(rp, rp)));
        float R = rp / nr;

        float zf; int ii;
        if (n == 0)        { zf = 1.0f; ii = 1; }
        else if (n <= NIN) { zf = z[b * NIN + n - 1]; ii = is_input[b * NIN + n - 1]; }
        else               { zf = 0.0f; ii = 0; }

        float V;
        if (ii > 0) {
            float x = __fmul_rn(PI_F, zf);
            V = __fadd_rn(__fmul_rn(-cosf(x), v0l), __fmul_rn(sinf(x), R));
        } else {
            V = R;
        }
        if (n == 0) V = v0l;
        V_g[((size_t)b * 1024 + n) * 32 + l] = V;
    }

    // free list (warp 31)
    if (w == 31) {
        int m = 0;
        for (int base = 1; base < 1024; base += 32) {
            int n = base + l;
            bool f = (n < 1024) && (n > NIN || is_input[b * NIN + n - 1] == 0);
            unsigned msk = __ballot_sync(0xffffffffu, f);
            if (f) {
                int pos = m + __popc(msk & ((1u << l) - 1u));
                list_g[b * 1024 + pos] = (unsigned short)n;
            }
            m += __popc(msk);
        }
        if (l == 0) cnt_g[b] = m;
    }
    __syncthreads();

    // VH fill: VH[b][m] = V_init[b][lst[m]]   (all 32 warps)
    int c = cnt_g[b];
    for (int m = w; m < c; m += 32) {
        int i = list_g[b * 1024 + m];
        VH_g[((size_t)b * 1024 + m) * 32 + l] = V_g[((size_t)b * 1024 + i) * 32 + l];
    }
}

// ---------------- mix kernel: S=8 batched, pipelined ----------------
__global__ void __launch_bounds__(544, 1)
mix_kernel(const float* __restrict__ C,
           const float* __restrict__ z,
           const int* __restrict__ is_input,
           float* __restrict__ out) {
    extern __shared__ __align__(16) float sm[];
    unsigned short* lstS = (unsigned short*)&sm[F_LST];

    const int b = blockIdx.x;
    const int tid = threadIdx.x;
    const int w = tid >> 5;
    const int l = tid & 31;
    const bool dotw = (w < 16);

    __shared__ int scnt;
    for (int idx = tid; idx < 1024; idx += 544)
        lstS[idx] = list_g[b * 1024 + idx];
    if (tid == 0) scnt = cnt_g[b];
    __syncthreads();
    const int cnt = scnt;
    const int total = cnt * SWEEPS;
    const int P = (total + S - 1) / S;

    // coupling tables svd[d][m] = C[lst[(m+d+1)%cnt], lst[m]], distance d+1 = 1..15
    for (int t = tid; t < 15 * cnt; t += 544) {
        int d = t / cnt;
        int m = t - d * cnt;
        int mp = m + d + 1; if (mp >= cnt) mp -= cnt;
        sm[F_SVD + d * 1024 + m] =
            __ldg(C + (size_t)lstS[mp] * NVARS + lstS[m]);
    }

    // V in registers: warp w owns rows [64w,64w+64), lane l = column l
    unsigned long long v2[32];
    if (dotw) {
#pragma unroll
        for (int p = 0; p < 32; p++) {
            int row = w * 64 + 2 * p;
            v2[p] = pk2(V_g[((size_t)b * 1024 + row) * 32 + l],
                        V_g[((size_t)b * 1024 + row + 1) * 32 + l]);
        }
    }
    __syncthreads();   // svd + lst ready

    // staging helper indices for 512 threads: row s = tid>>6, chunk c = tid&63 (64B each)
    const int st_s = tid >> 6;
    const int st_c = (tid & 63) * 16;   // float offset within row

    // prologue staging: G1 -> slot 1, G2 -> slot 2
    if (tid < 512) {
        int mq = S + st_s; if (mq >= cnt) mq -= cnt;
        const float* src = C + (size_t)lstS[mq] * NVARS + st_c;
        float* dst = &sm[F_CBUF + (8 + st_s) * 1024 + st_c];
#pragma unroll
        for (int k = 0; k < 4; k++)
            __pipeline_memcpy_async(dst + k * 4, src + k * 4, 16);
    }
    __pipeline_commit();
    if (tid < 512) {
        int mq = 2 * S + st_s; if (mq >= cnt) mq -= cnt;
        const float* src = C + (size_t)lstS[mq] * NVARS + st_c;
        float* dst = &sm[F_CBUF + (16 + st_s) * 1024 + st_c];
#pragma unroll
        for (int k = 0; k < 4; k++)
            __pipeline_memcpy_async(dst + k * 4, src + k * 4, 16);
    }
    __pipeline_commit();

    // prologue dots for G0 from gmem
    if (dotw) {
#pragma unroll
        for (int s = 0; s < S; s++) {
            const ulonglong2* Cp = reinterpret_cast<const ulonglong2*>(
                C + (size_t)lstS[s] * NVARS + w * 64);
            sm[F_PT + 0 * 4096 + s * 512 + w * 32 + l] = dot_row(Cp, v2);
        }
    }

    // reducer initial vold
    float dvP[S] = {0.f, 0.f, 0.f, 0.f, 0.f, 0.f, 0.f, 0.f};
    float vold_cur[S];
    if (w == 16) {
#pragma unroll
        for (int s = 0; s < S; s++)
            vold_cur[s] = VH_g[((size_t)b * 1024 + s) * 32 + l];
    }

    __pipeline_wait_prior(1);
    __syncthreads();

    int m_prev = 0, m_cur = 0, m_n1 = S % cnt, m_stage = (3 * S) % cnt;

    for (int p = 0; p < P; p++) {
        const int rd = p & 1, wr = (p + 1) & 1;

        // stage G_{p+3} into ring slot p%3
        if (tid < 512) {
            int mq = m_stage + st_s; if (mq >= cnt) mq -= cnt;
            const float* src = C + (size_t)lstS[mq] * NVARS + st_c;
            float* dst = &sm[F_CBUF + ((p % 3) * 8 + st_s) * 1024 + st_c];
#pragma unroll
            for (int k = 0; k < 4; k++)
                __pipeline_memcpy_async(dst + k * 4, src + k * 4, 16);
        }
        __pipeline_commit();

        if (dotw) {
            // apply previous phase's updates (G_{p-1})
            if (p > 0) {
#pragma unroll
                for (int s = 0; s < S; s++) {
                    int mp = m_prev + s; if (mp >= cnt) mp -= cnt;
                    int i = lstS[mp];
                    if (w == (i >> 6))
                        insert_pred(v2, i & 63, sm[F_VNB + wr * 256 + s * 32 + l]);
                }
            }
            // dots for G_{p+1} from staged ring slot (p+1)%3
            int slotr = ((p + 1) % 3) * 8;
#pragma unroll
            for (int s = 0; s < S; s++) {
                const ulonglong2* Cs = reinterpret_cast<const ulonglong2*>(
                    &sm[F_CBUF + (slotr + s) * 1024 + w * 64]);
                sm[F_PT + wr * 4096 + s * 512 + w * 32 + l] = dot_row(Cs, v2);
            }
        } else if (w == 16) {
            // prefetch vold for G_{p+1} (off-chain)
            float vold_nxt[S];
#pragma unroll
            for (int s = 0; s < S; s++) {
                int mq = m_n1 + s; if (mq >= cnt) mq -= cnt;
                vold_nxt[s] = VH_g[((size_t)b * 1024 + mq) * 32 + l];
            }
            // base sums: tree + prev-group corrections (off-chain)
            float base[S];
#pragma unroll
            for (int s = 0; s < S; s++) {
                const float* pr = &sm[F_PT + rd * 4096 + s * 512];
                float t0 = pr[0 * 32 + l],  t1 = pr[1 * 32 + l];
                float t2 = pr[2 * 32 + l],  t3 = pr[3 * 32 + l];
                float t4 = pr[4 * 32 + l],  t5 = pr[5 * 32 + l];
                float t6 = pr[6 * 32 + l],  t7 = pr[7 * 32 + l];
                float t8 = pr[8 * 32 + l],  t9 = pr[9 * 32 + l];
                float ta = pr[10 * 32 + l], tb = pr[11 * 32 + l];
                float tc = pr[12 * 32 + l], td = pr[13 * 32 + l];
                float te = pr[14 * 32 + l], tf = pr[15 * 32 + l];
                float g = (((t0 + t1) + (t2 + t3)) + ((t4 + t5) + (t6 + t7)))
                        + (((t8 + t9) + (ta + tb)) + ((tc + td) + (te + tf)));
#pragma unroll
                for (int sp = 0; sp < S; sp++) {
                    int d = S + s - sp;                 // 1..15
                    int mq = m_prev + sp; if (mq >= cnt) mq -= cnt;
                    g = fmaf(sm[F_SVD + (d - 1) * 1024 + mq], dvP[sp], g);
                }
                base[s] = g;
            }
            // serial chain: intra-group corrections + normalize
            float dv_new[S];
#pragma unroll
            for (int s = 0; s < S; s++) {
                float g = base[s];
#pragma unroll
                for (int sp = 0; sp < S; sp++)
                    if (sp < s) {
                        int d = s - sp;                 // 1..7
                        int mq = m_cur + sp; if (mq >= cnt) mq -= cnt;
                        g = fmaf(sm[F_SVD + (d - 1) * 1024 + mq], dv_new[sp], g);
                    }
                float ss = warp_sum(g * g);
                ss = fmaxf(ss, 1e-24f);
                float vn = -g * rsqrtf(ss);
                sm[F_VNB + rd * 256 + s * 32 + l] = vn;
                int mq = m_cur + s; if (mq >= cnt) mq -= cnt;
                VH_g[((size_t)b * 1024 + mq) * 32 + l] = vn;
                dv_new[s] = vn - vold_cur[s];
            }
#pragma unroll
            for (int s = 0; s < S; s++) { dvP[s] = dv_new[s]; vold_cur[s] = vold_nxt[s]; }
        }

        __pipeline_wait_prior(1);
        __syncthreads();

        m_prev = m_cur; m_cur = m_n1;
        m_n1 += S; if (m_n1 >= cnt) m_n1 -= cnt;
        m_stage += S; if (m_stage >= cnt) m_stage -= cnt;
    }

    // apply pending last-phase updates (guard stream index < total)
    if (dotw) {
        int baseT = S * (P - 1);
        int basem = baseT % cnt;
        int vb = (P - 1) & 1;
#pragma unroll
        for (int s = 0; s < S; s++) {
            if (baseT + s < total) {
                int mp = basem + s; if (mp >= cnt) mp -= cnt;
                int i = lstS[mp];
                if (w == (i >> 6))
                    insert_pred(v2, i & 63, sm[F_VNB + vb * 256 + s * 32 + l]);
            }
        }
    }

    // ---------------- epilogue: z_out[:, 1:769] ----------------
    if (dotw) {
        float v0l = v0_g[b * 32 + l];
        const float CLO = (float)(-1.0 + 1e-7);
        const float CHI = (float)( 1.0 - 1e-7);
#pragma unroll
        for (int j = 0; j < 64; j++) {
            int n = w * 64 + j;
            if (n >= 1 && n <= NIN) {
                float x, y; up2(v2[j >> 1], x, y);
                float Vv = (j & 1) ? y : x;
                float d = warp_sum(__fmul_rn(Vv, v0l));
                if (l == 0) {
                    int idx = b * NIN + n - 1;
                    float res;
                    if (is_input[idx] != 0) {
                        res = z[idx];
                    } else {
                        float ca = fminf(fmaxf(-d, CLO), CHI);
                        res = acosf(ca) / PI_F;
                    }
                    out[idx] = res;
                }
            }
        }
    }
}

// ---------------- launcher ----------------
extern "C" void kernel_launch(void* const* d_in, const int* in_sizes, int n_in,
                              void* d_out, int out_size) {
    const float* C        = (const float*)d_in[0];
    const float* z        = (const float*)d_in[1];
    const int*   is_input = (const int*)d_in[2];
    float* out = (float*)d_out;

    cudaFuncSetAttribute(mix_kernel,
                         cudaFuncAttributeMaxDynamicSharedMemorySize, SMEM_BYTES);

    init_kernel<<<BATCH, 1024>>>(z, is_input);
    mix_kernel<<<BATCH, 544, SMEM_BYTES>>>(C, z, is_input, out);
}

// round 12
// speedup vs baseline: 1.4407x; 1.2986x over previous
#include <cuda_runtime.h>
#include <cuda_pipeline.h>
#include <cstdint>
#include <math.h>

#define NVARS 1024
#define BATCH 64
#define KDIM  32
#define NIN   768
#define SWEEPS 10
#define PI_F 3.14159274101257324f
#define S 4

// dynamic smem layout (floats) — half-rows (512 floats) per CTA
#define F_CBUF 0            // 12 half-rows * 512  (3-group x 4-row ring)
#define F_SVD  6144         // 7 * 1024 coupling tables (CTA0 only)
#define F_PT   13312        // 2 * 4 * 512 partials (CTA0 authoritative)
#define F_VNB  17408        // 2 * 4 * 32 vn broadcast (both CTAs)
#define F_LST  17664        // 1024 ushort = 512 floats
#define SMEM_FLOATS 18176
#define SMEM_BYTES (SMEM_FLOATS * 4)   // ~72.7 KB

// ---------------- persistent scratch (no runtime allocation) ----------------
__device__ float V_g[BATCH * NVARS * KDIM];     // 8 MB
__device__ float VH_g[BATCH * NVARS * KDIM];    // 8 MB value-history by list position
__device__ float v0_g[BATCH * KDIM];
__device__ unsigned short list_g[BATCH * NVARS];
__device__ int cnt_g[BATCH];

// ---------------- f32x2 helpers ----------------
__device__ __forceinline__ void ffma2(unsigned long long &d, unsigned long long a,
                                      unsigned long long b) {
    asm("fma.rn.f32x2 %0, %1, %2, %3;" : "=l"(d) : "l"(a), "l"(b), "l"(d));
}
__device__ __forceinline__ void fadd2(unsigned long long &d, unsigned long long a,
                                      unsigned long long b) {
    asm("add.rn.f32x2 %0, %1, %2;" : "=l"(d) : "l"(a), "l"(b));
}
__device__ __forceinline__ unsigned long long pk2(float lo, float hi) {
    unsigned long long r;
    asm("mov.b64 %0, {%1, %2};" : "=l"(r) : "f"(lo), "f"(hi));
    return r;
}
__device__ __forceinline__ void up2(unsigned long long v, float &lo, float &hi) {
    asm("mov.b64 {%0, %1}, %2;" : "=f"(lo), "=f"(hi) : "l"(v));
}

__device__ __forceinline__ float warp_sum(float v) {
#pragma unroll
    for (int off = 16; off; off >>= 1)
        v += __shfl_xor_sync(0xffffffffu, v, off);
    return v;
}

__device__ __forceinline__ uint32_t smem_u32(const void* p) {
    uint32_t a;
    asm("{ .reg .u64 t; cvta.to.shared.u64 t, %1; cvt.u32.u64 %0, t; }"
        : "=r"(a) : "l"(p));
    return a;
}

// store one f32 into the peer CTA's smem at the same offset
__device__ __forceinline__ void sts_remote(uint32_t laddr, uint32_t trank, float v) {
    uint32_t raddr;
    asm("mapa.shared::cluster.u32 %0, %1, %2;" : "=r"(raddr) : "r"(laddr), "r"(trank));
    asm volatile("st.shared::cluster.b32 [%0], %1;"
                 :: "r"(raddr), "r"(__float_as_uint(v)) : "memory");
}

#define CLUSTER_SYNC() do { \
    asm volatile("barrier.cluster.arrive.aligned;" ::: "memory"); \
    asm volatile("barrier.cluster.wait.aligned;" ::: "memory"); \
} while (0)

// half-row dot: 64 floats (16 ulonglong2) against v2
__device__ __forceinline__ float dot_row(const ulonglong2* __restrict__ Cp,
                                         const unsigned long long (&v2)[32]) {
    unsigned long long a0 = 0ull, a1 = 0ull, a2 = 0ull, a3 = 0ull;
#pragma unroll
    for (int q = 0; q < 16; q++) {
        ulonglong2 cc = Cp[q];
        ffma2(((q & 1) ? a2 : a0), cc.x, v2[2 * q]);
        ffma2(((q & 1) ? a3 : a1), cc.y, v2[2 * q + 1]);
    }
    fadd2(a0, a0, a2); fadd2(a1, a1, a3); fadd2(a0, a0, a1);
    float x, y; up2(a0, x, y);
    return x + y;
}

// predicated-chain insert (verified form)
__device__ __forceinline__ void insert_pred(unsigned long long (&v2)[32], int j, float vn) {
    int p0 = j >> 1;
#pragma unroll
    for (int p = 0; p < 32; p++)
        if (p == p0) {
            float x, y; up2(v2[p], x, y);
            if (j & 1) y = vn; else x = vn;
            v2[p] = pk2(x, y);
        }
}

// ---------------- threefry2x32 core, exact JAX schedule ----------------
__device__ __forceinline__ void tf2x32(unsigned k0, unsigned k1,
                                       unsigned x0, unsigned x1,
                                       unsigned &y0, unsigned &y1) {
    unsigned ks2 = k0 ^ k1 ^ 0x1BD11BDAu;
    x0 += k0; x1 += k1;
#define TFR(r) { x0 += x1; x1 = (x1 << r) | (x1 >> (32 - r)); x1 ^= x0; }
    TFR(13) TFR(15) TFR(26) TFR(6)  x0 += k1;  x1 += ks2 + 1u;
    TFR(17) TFR(29) TFR(16) TFR(24) x0 += ks2; x1 += k0 + 2u;
    TFR(13) TFR(15) TFR(26) TFR(6)  x0 += k0;  x1 += k1 + 3u;
    TFR(17) TFR(29) TFR(16) TFR(24) x0 += k1;  x1 += ks2 + 4u;
    TFR(13) TFR(15) TFR(26) TFR(6)  x0 += ks2; x1 += k0 + 5u;
#undef TFR
    y0 = x0; y1 = x1;
}

// PARTITIONABLE threefry (modern JAX default)
__device__ __forceinline__ void derive_keys(unsigned &k1a, unsigned &k1b,
                                            unsigned &k2a, unsigned &k2b) {
    tf2x32(0u, 42u, 0u, 0u, k1a, k1b);
    tf2x32(0u, 42u, 0u, 1u, k2a, k2b);
}

__device__ __forceinline__ unsigned tf_bits(unsigned ka, unsigned kb, unsigned e) {
    unsigned y0, y1;
    tf2x32(ka, kb, 0u, e, y0, y1);
    return y0 ^ y1;
}

__device__ __forceinline__ float bits_to_normal(unsigned bits) {
    float u01 = __fadd_rn(__uint_as_float((bits >> 9) | 0x3F800000u), -1.0f);
    float u = __fadd_rn(__fmul_rn(u01, 2.0f), -0.99999994f);
    u = fmaxf(u, -0.99999994f);
    float x = u;
    float xx = __fmul_rn(x, x);
    float w = -log1pf(-xx);
    float p;
    if (w < 5.0f) {
        w = __fadd_rn(w, -2.5f);
        p = 2.81022636e-08f;
        p = __fadd_rn(__fmul_rn(p, w), 3.43273939e-07f);
        p = __fadd_rn(__fmul_rn(p, w), -3.5233877e-06f);
        p = __fadd_rn(__fmul_rn(p, w), -4.39150654e-06f);
        p = __fadd_rn(__fmul_rn(p, w), 0.00021858087f);
        p = __fadd_rn(__fmul_rn(p, w), -0.00125372503f);
        p = __fadd_rn(__fmul_rn(p, w), -0.00417768164f);
        p = __fadd_rn(__fmul_rn(p, w), 0.246640727f);
        p = __fadd_rn(__fmul_rn(p, w), 1.50140941f);
    } else {
        w = __fadd_rn(sqrtf(w), -3.0f);
        p = -0.000200214257f;
        p = __fadd_rn(__fmul_rn(p, w), 0.000100950558f);
        p = __fadd_rn(__fmul_rn(p, w), 0.00134934322f);
        p = __fadd_rn(__fmul_rn(p, w), -0.00367342844f);
        p = __fadd_rn(__fmul_rn(p, w), 0.00573950773f);
        p = __fadd_rn(__fmul_rn(p, w), -0.0076224613f);
        p = __fadd_rn(__fmul_rn(p, w), 0.00943887047f);
        p = __fadd_rn(__fmul_rn(p, w), 1.00167406f);
        p = __fadd_rn(__fmul_rn(p, w), 2.83297682f);
    }
    return __fmul_rn(1.41421354f, __fmul_rn(p, x));
}

// ---------------- fused init kernel: one CTA per batch, 1024 threads ----------------
__global__ void __launch_bounds__(1024, 1)
init_kernel(const float* __restrict__ z, const int* __restrict__ is_input) {
    __shared__ float v0s[32];
    const int b = blockIdx.x;
    const int w = threadIdx.x >> 5;
    const int l = threadIdx.x & 31;
    unsigned k1a, k1b, k2a, k2b; derive_keys(k1a, k1b, k2a, k2b);

    if (w == 0) {
        float n = bits_to_normal(tf_bits(k1a, k1b, (unsigned)(b * 32 + l)));
        float ss = warp_sum(__fmul_rn(n, n));
        float v0 = n / sqrtf(ss);
        v0s[l] = v0;
        v0_g[b * 32 + l] = v0;
    }
    __syncthreads();
    float v0l = v0s[l];

#pragma unroll 1
    for (int k = 0; k < 32; k++) {
        int n = w * 32 + k;
        unsigned e = ((unsigned)(b * 1024 + n)) * 32u + (unsigned)l;
        float r = bits_to_normal(tf_bits(k2a, k2b, e));
        float d = warp_sum(__fmul_rn(r, v0l));
        float rp = __fadd_rn(r, -__fmul_rn(d, v0l));
        float nr = sqrtf(warp_sum(__fmul_rn(rp, rp)));
        float R = rp / nr;

        float zf; int ii;
        if (n == 0)        { zf = 1.0f; ii = 1; }
        else if (n <= NIN) { zf = z[b * NIN + n - 1]; ii = is_input[b * NIN + n - 1]; }
        else               { zf = 0.0f; ii = 0; }

        float V;
        if (ii > 0) {
            float x = __fmul_rn(PI_F, zf);
            V = __fadd_rn(__fmul_rn(-cosf(x), v0l), __fmul_rn(sinf(x), R));
        } else {
            V = R;
        }
        if (n == 0) V = v0l;
        V_g[((size_t)b * 1024 + n) * 32 + l] = V;
    }

    // free list (warp 31)
    if (w == 31) {
        int m = 0;
        for (int base = 1; base < 1024; base += 32) {
            int n = base + l;
            bool f = (n < 1024) && (n > NIN || is_input[b * NIN + n - 1] == 0);
            unsigned msk = __ballot_sync(0xffffffffu, f);
            if (f) {
                int pos = m + __popc(msk & ((1u << l) - 1u));
                list_g[b * 1024 + pos] = (unsigned short)n;
            }
            m += __popc(msk);
        }
        if (l == 0) cnt_g[b] = m;
    }
    __syncthreads();

    // VH fill: VH[b][m] = V_init[b][lst[m]]
    int c = cnt_g[b];
    for (int m = w; m < c; m += 32) {
        int i = list_g[b * 1024 + m];
        VH_g[((size_t)b * 1024 + m) * 32 + l] = V_g[((size_t)b * 1024 + i) * 32 + l];
    }
}

// ---------------- mix kernel: 2-CTA cluster per batch, S=4 phases ----------------
__global__ void __launch_bounds__(288, 1) __cluster_dims__(2, 1, 1)
mix_kernel(const float* __restrict__ C,
           const float* __restrict__ z,
           const int* __restrict__ is_input,
           float* __restrict__ out) {
    extern __shared__ __align__(16) float sm[];
    unsigned short* lstS = (unsigned short*)&sm[F_LST];

    uint32_t rank;
    asm("mov.u32 %0, %%cluster_ctarank;" : "=r"(rank));
    const int b = blockIdx.x >> 1;
    const int tid = threadIdx.x;
    const int w = tid >> 5;           // 0..8
    const int l = tid & 31;
    const bool dotw = (w < 8);
    const bool redw = (rank == 0) && (w == 8);
    const uint32_t smb = smem_u32(sm);

    __shared__ int scnt;
    for (int idx = tid; idx < 1024; idx += 288)
        lstS[idx] = list_g[b * 1024 + idx];
    if (tid == 0) scnt = cnt_g[b];
    __syncthreads();
    const int cnt = scnt;
    const int total = cnt * SWEEPS;
    const int P = (total + S - 1) / S;

    // coupling tables (CTA0 only): svd[d][m] = C[lst[(m+d+1)%cnt], lst[m]]
    if (rank == 0) {
        for (int t = tid; t < 7 * cnt; t += 288) {
            int d = t / cnt;
            int m = t - d * cnt;
            int mp = m + d + 1; if (mp >= cnt) mp -= cnt;
            sm[F_SVD + d * 1024 + m] =
                __ldg(C + (size_t)lstS[mp] * NVARS + lstS[m]);
        }
    }

    // V registers: CTA rank owns rows [512*rank, 512*rank+512), warp w -> 64 rows
    unsigned long long v2[32];
    const int rowbase = (int)rank * 512 + w * 64;
    if (dotw) {
#pragma unroll
        for (int p = 0; p < 32; p++) {
            int row = rowbase + 2 * p;
            v2[p] = pk2(V_g[((size_t)b * 1024 + row) * 32 + l],
                        V_g[((size_t)b * 1024 + row + 1) * 32 + l]);
        }
    }
    __syncthreads();   // lst/svd ready (intra-CTA)

    // staging: per phase 4 half-rows (512 floats each); tid<256: s=tid>>6, c=tid&63,
    // each thread copies chunks c and c+64 (16 B each)
    const int st_s = tid >> 6;
    const int st_c = (tid & 63) * 4;  // float offset of first chunk

    // prologue staging: G1 -> slots 4..7, G2 -> slots 8..11
    if (tid < 256) {
        int mq = (4 + st_s) % cnt;
        const float* src = C + (size_t)lstS[mq] * NVARS + rank * 512;
        float* dst = &sm[F_CBUF + (4 + st_s) * 512];
        __pipeline_memcpy_async(dst + st_c, src + st_c, 16);
        __pipeline_memcpy_async(dst + st_c + 256, src + st_c + 256, 16);
    }
    __pipeline_commit();
    if (tid < 256) {
        int mq = (8 + st_s) % cnt;
        const float* src = C + (size_t)lstS[mq] * NVARS + rank * 512;
        float* dst = &sm[F_CBUF + (8 + st_s) * 512];
        __pipeline_memcpy_async(dst + st_c, src + st_c, 16);
        __pipeline_memcpy_async(dst + st_c + 256, src + st_c + 256, 16);
    }
    __pipeline_commit();

    // prologue dots for G0 from gmem
    if (dotw) {
#pragma unroll
        for (int s = 0; s < S; s++) {
            const ulonglong2* Cp = reinterpret_cast<const ulonglong2*>(
                C + (size_t)lstS[s] * NVARS + rowbase);
            float part = dot_row(Cp, v2);
            int slot = F_PT + 0 * 2048 + s * 512 + ((int)rank * 8 + w) * 32 + l;
            if (rank == 0) sm[slot] = part;
            else           sts_remote(smb + slot * 4, 0, part);
        }
    }

    // reducer initial vold
    float dvP[S] = {0.f, 0.f, 0.f, 0.f};
    float vold_cur[S];
    if (redw) {
#pragma unroll
        for (int s = 0; s < S; s++)
            vold_cur[s] = VH_g[((size_t)b * 1024 + s) * 32 + l];
    }

    __pipeline_wait_prior(1);
    CLUSTER_SYNC();

    int m_prev = 0, m_cur = 0, m_n1 = S % cnt, m_stage = (3 * S) % cnt;

    for (int p = 0; p < P; p++) {
        const int rd = p & 1, wr = (p + 1) & 1;

        // stage G_{p+3} into ring slot p%3
        if (tid < 256) {
            int mq = m_stage + st_s; if (mq >= cnt) mq -= cnt;
            const float* src = C + (size_t)lstS[mq] * NVARS + rank * 512;
            float* dst = &sm[F_CBUF + ((p % 3) * 4 + st_s) * 512];
            __pipeline_memcpy_async(dst + st_c, src + st_c, 16);
            __pipeline_memcpy_async(dst + st_c + 256, src + st_c + 256, 16);
        }
        __pipeline_commit();

        if (dotw) {
            // apply previous phase's updates (G_{p-1})
            if (p > 0) {
#pragma unroll
                for (int s = 0; s < S; s++) {
                    int mp = m_prev + s; if (mp >= cnt) mp -= cnt;
                    int i = lstS[mp];
                    if ((i >> 6) == w + 8 * (int)rank)
                        insert_pred(v2, i & 63, sm[F_VNB + wr * 128 + s * 32 + l]);
                }
            }
            // dots for G_{p+1} from staged ring slot (p+1)%3
            int slotr = ((p + 1) % 3) * 4;
#pragma unroll
            for (int s = 0; s < S; s++) {
                const ulonglong2* Cs = reinterpret_cast<const ulonglong2*>(
                    &sm[F_CBUF + (slotr + s) * 512 + w * 64]);
                float part = dot_row(Cs, v2);
                int slot = F_PT + wr * 2048 + s * 512 + ((int)rank * 8 + w) * 32 + l;
                if (rank == 0) sm[slot] = part;
                else           sts_remote(smb + slot * 4, 0, part);
            }
        } else if (redw) {
            // prefetch vold for G_{p+1}
            float vold_nxt[S];
#pragma unroll
            for (int s = 0; s < S; s++) {
                int mq = m_n1 + s; if (mq >= cnt) mq -= cnt;
                vold_nxt[s] = VH_g[((size_t)b * 1024 + mq) * 32 + l];
            }
            // base sums: 16-way tree + prev-group corrections
            float base[S];
#pragma unroll
            for (int s = 0; s < S; s++) {
                const float* pr = &sm[F_PT + rd * 2048 + s * 512];
                float t0 = pr[0 * 32 + l],  t1 = pr[1 * 32 + l];
                float t2 = pr[2 * 32 + l],  t3 = pr[3 * 32 + l];
                float t4 = pr[4 * 32 + l],  t5 = pr[5 * 32 + l];
                float t6 = pr[6 * 32 + l],  t7 = pr[7 * 32 + l];
                float t8 = pr[8 * 32 + l],  t9 = pr[9 * 32 + l];
                float ta = pr[10 * 32 + l], tb = pr[11 * 32 + l];
                float tc = pr[12 * 32 + l], td = pr[13 * 32 + l];
                float te = pr[14 * 32 + l], tf = pr[15 * 32 + l];
                float g = (((t0 + t1) + (t2 + t3)) + ((t4 + t5) + (t6 + t7)))
                        + (((t8 + t9) + (ta + tb)) + ((tc + td) + (te + tf)));
#pragma unroll
                for (int sp = 0; sp < S; sp++) {
                    int d = S + s - sp;                 // 1..7
                    int mq = m_prev + sp; if (mq >= cnt) mq -= cnt;
                    g = fmaf(sm[F_SVD + (d - 1) * 1024 + mq], dvP[sp], g);
                }
                base[s] = g;
            }
            // serial chain: intra-group corrections + normalize
            float dv_new[S];
#pragma unroll
            for (int s = 0; s < S; s++) {
                float g = base[s];
#pragma unroll
                for (int sp = 0; sp < S; sp++)
                    if (sp < s) {
                        int d = s - sp;                 // 1..3
                        int mq = m_cur + sp; if (mq >= cnt) mq -= cnt;
                        g = fmaf(sm[F_SVD + (d - 1) * 1024 + mq], dv_new[sp], g);
                    }
                float ss = warp_sum(g * g);
                ss = fmaxf(ss, 1e-24f);
                float vn = -g * rsqrtf(ss);
                int voff = F_VNB + rd * 128 + s * 32 + l;
                sm[voff] = vn;
                sts_remote(smb + voff * 4, 1, vn);      // broadcast to CTA1
                int mq = m_cur + s; if (mq >= cnt) mq -= cnt;
                VH_g[((size_t)b * 1024 + mq) * 32 + l] = vn;
                dv_new[s] = vn - vold_cur[s];
            }
#pragma unroll
            for (int s = 0; s < S; s++) { dvP[s] = dv_new[s]; vold_cur[s] = vold_nxt[s]; }
        }

        __pipeline_wait_prior(1);
        CLUSTER_SYNC();

        m_prev = m_cur; m_cur = m_n1;
        m_n1 += S; if (m_n1 >= cnt) m_n1 -= cnt;
        m_stage += S; if (m_stage >= cnt) m_stage -= cnt;
    }

    // apply pending last-phase updates
    if (dotw) {
        int baseT = S * (P - 1);
        int basem = baseT % cnt;
        int vb = (P - 1) & 1;
#pragma unroll
        for (int s = 0; s < S; s++) {
            if (baseT + s < total) {
                int mp = basem + s; if (mp >= cnt) mp -= cnt;
                int i = lstS[mp];
                if ((i >> 6) == w + 8 * (int)rank)
                    insert_pred(v2, i & 63, sm[F_VNB + vb * 128 + s * 32 + l]);
            }
        }
    }

    // ---------------- epilogue: z_out[:, 1:769] ----------------
    if (dotw) {
        float v0l = v0_g[b * 32 + l];
        const float CLO = (float)(-1.0 + 1e-7);
        const float CHI = (float)( 1.0 - 1e-7);
#pragma unroll
        for (int j = 0; j < 64; j++) {
            int n = rowbase + j;
            if (n >= 1 && n <= NIN) {
                float x, y; up2(v2[j >> 1], x, y);
                float Vv = (j & 1) ? y : x;
                float d = warp_sum(__fmul_rn(Vv, v0l));
                if (l == 0) {
                    int idx = b * NIN + n - 1;
                    float res;
                    if (is_input[idx] != 0) {
                        res = z[idx];
                    } else {
                        float ca = fminf(fmaxf(-d, CLO), CHI);
                        res = acosf(ca) / PI_F;
                    }
                    out[idx] = res;
                }
            }
        }
    }
}

// ---------------- launcher ----------------
extern "C" void kernel_launch(void* const* d_in, const int* in_sizes, int n_in,
                              void* d_out, int out_size) {
    const float* C        = (const float*)d_in[0];
    const float* z        = (const float*)d_in[1];
    const int*   is_input = (const int*)d_in[2];
    float* out = (float*)d_out;

    cudaFuncSetAttribute(mix_kernel,
                         cudaFuncAttributeMaxDynamicSharedMemorySize, SMEM_BYTES);

    init_kernel<<<BATCH, 1024>>>(z, is_input);
    mix_kernel<<<2 * BATCH, 288, SMEM_BYTES>>>(C, z, is_input, out);
}